// round 2
// baseline (speedup 1.0000x reference)
#include <cuda_runtime.h>
#include <cuda_bf16.h>
#include <cstdint>

// Problem constants
#define D_MODEL 768
#define D_INNER 768
#define D_STATE 8
#define D_CONV  3
#define BATCH   4
#define SEQ     8192
#define M_TOT   (BATCH * SEQ)        // 32768
#define N_IN    (2 * D_INNER)        // 1536
#define CHUNK   128
#define NCHUNK  (SEQ / CHUNK)        // 64

// Scratch (static __device__ arrays per allocation rules)
__device__ float g_XZ[(size_t)M_TOT * N_IN];        // [B*L, 1536] = x @ W_in
__device__ float g_YZ[(size_t)M_TOT * D_INNER];     // [B*L, 768]  = y * silu(z)
__device__ float g_CS[(size_t)BATCH * NCHUNK * D_INNER]; // chunk sums / exclusive offsets

// ---------------------------------------------------------------------------
// Classic fp32 SGEMM: 128x128 blocktile, BK=8, 256 threads, 8x8 microtile.
// A row-major [M,K], B row-major [K,N], C row-major [M,N]. All dims divide tiles.
// ---------------------------------------------------------------------------
#define BM 128
#define BN 128
#define BK 8
#define TM 8
#define TN 8

__global__ __launch_bounds__(256) void sgemm_kernel(
    const float* __restrict__ A, const float* __restrict__ B,
    float* __restrict__ C, int M, int N, int K)
{
    __shared__ float As[BK][BM];
    __shared__ float Bs[BK][BN];

    const int tid = threadIdx.x;
    const int bm = blockIdx.y;
    const int bn = blockIdx.x;

    const float* Ab = A + (size_t)bm * BM * K;
    const float* Bb = B + (size_t)bn * BN;

    // A tile load: 128x8 floats = 256 float4; thread -> (row = tid/2, col4 = (tid&1)*4)
    const int arow = tid >> 1;
    const int acol = (tid & 1) * 4;
    // B tile load: 8x128 floats = 256 float4; thread -> (row = tid/32, col = (tid&31)*4)
    const int brow = tid >> 5;
    const int bcol = (tid & 31) * 4;

    const int ty = (tid >> 4) * TM;   // 0..120
    const int tx = (tid & 15) * TN;   // 0..120

    float acc[TM][TN] = {};

    for (int k0 = 0; k0 < K; k0 += BK) {
        float4 av = *(const float4*)(Ab + (size_t)arow * K + k0 + acol);
        As[acol + 0][arow] = av.x;
        As[acol + 1][arow] = av.y;
        As[acol + 2][arow] = av.z;
        As[acol + 3][arow] = av.w;
        float4 bv = *(const float4*)(Bb + (size_t)(k0 + brow) * N + bcol);
        *(float4*)&Bs[brow][bcol] = bv;
        __syncthreads();

        #pragma unroll
        for (int k = 0; k < BK; k++) {
            float a[TM], b[TN];
            *(float4*)&a[0] = *(const float4*)&As[k][ty];
            *(float4*)&a[4] = *(const float4*)&As[k][ty + 4];
            *(float4*)&b[0] = *(const float4*)&Bs[k][tx];
            *(float4*)&b[4] = *(const float4*)&Bs[k][tx + 4];
            #pragma unroll
            for (int i = 0; i < TM; i++)
                #pragma unroll
                for (int j = 0; j < TN; j++)
                    acc[i][j] = fmaf(a[i], b[j], acc[i][j]);
        }
        __syncthreads();
    }

    float* Cb = C + (size_t)(bm * BM) * N + (size_t)bn * BN;
    #pragma unroll
    for (int i = 0; i < TM; i++) {
        #pragma unroll
        for (int j = 0; j < TN; j += 4) {
            float4 v = make_float4(acc[i][j], acc[i][j + 1], acc[i][j + 2], acc[i][j + 3]);
            *(float4*)(Cb + (size_t)(ty + i) * N + tx + j) = v;
        }
    }
}

// ---------------------------------------------------------------------------
// silu helper
// ---------------------------------------------------------------------------
__device__ __forceinline__ float silu_f(float v) {
    return v / (1.0f + __expf(-v));
}

// ---------------------------------------------------------------------------
// Pass A: per-chunk sums of u = silu(conv3(xc) + bias), conv fused via register
// rolling. Block = 768 threads (one per channel), grid = (NCHUNK, BATCH).
// ---------------------------------------------------------------------------
__global__ __launch_bounds__(768) void scan_partial_kernel(
    const float* __restrict__ xz,
    const float* __restrict__ convw, const float* __restrict__ convb,
    float* __restrict__ csum)
{
    const int c = threadIdx.x;
    const int chunk = blockIdx.x;
    const int b = blockIdx.y;
    const int t0 = chunk * CHUNK;

    const float w0 = convw[c * 3 + 0];
    const float w1 = convw[c * 3 + 1];
    const float w2 = convw[c * 3 + 2];
    const float cb = convb[c];

    const size_t base = ((size_t)b * SEQ) * N_IN + c;

    float xm2 = 0.0f, xm1 = 0.0f;
    if (t0 >= 2) {
        xm2 = xz[base + (size_t)(t0 - 2) * N_IN];
        xm1 = xz[base + (size_t)(t0 - 1) * N_IN];
    }

    float s = 0.0f;
    #pragma unroll 4
    for (int t = t0; t < t0 + CHUNK; t++) {
        float x0 = xz[base + (size_t)t * N_IN];
        float v = fmaf(w0, xm2, fmaf(w1, xm1, fmaf(w2, x0, cb)));
        s += silu_f(v);
        xm2 = xm1;
        xm1 = x0;
    }
    csum[((size_t)b * NCHUNK + chunk) * D_INNER + c] = s;
}

// ---------------------------------------------------------------------------
// Pass B: in-place exclusive scan of chunk sums per (b,c). 3072 columns.
// ---------------------------------------------------------------------------
__global__ __launch_bounds__(256) void scan_offsets_kernel(float* __restrict__ csum)
{
    const int idx = blockIdx.x * blockDim.x + threadIdx.x; // b*768 + c
    if (idx >= BATCH * D_INNER) return;
    const int b = idx / D_INNER;
    const int c = idx % D_INNER;
    float run = 0.0f;
    for (int k = 0; k < NCHUNK; k++) {
        size_t p = ((size_t)b * NCHUNK + k) * D_INNER + c;
        float v = csum[p];
        csum[p] = run;
        run += v;
    }
}

// ---------------------------------------------------------------------------
// Pass C: recompute u, accumulate running cumsum (offset + local), apply
// y = cum*BC + u*D, multiply silu(z), write YZ coalesced.
// ---------------------------------------------------------------------------
__global__ __launch_bounds__(768) void scan_apply_kernel(
    const float* __restrict__ xz,
    const float* __restrict__ convw, const float* __restrict__ convb,
    const float* __restrict__ Bm, const float* __restrict__ Cm,
    const float* __restrict__ Dv,
    const float* __restrict__ csum,
    float* __restrict__ yz)
{
    const int c = threadIdx.x;
    const int chunk = blockIdx.x;
    const int b = blockIdx.y;
    const int t0 = chunk * CHUNK;

    const float w0 = convw[c * 3 + 0];
    const float w1 = convw[c * 3 + 1];
    const float w2 = convw[c * 3 + 2];
    const float cb = convb[c];

    float bc = 0.0f;
    #pragma unroll
    for (int s = 0; s < D_STATE; s++)
        bc = fmaf(Bm[c * D_STATE + s], Cm[c * D_STATE + s], bc);
    const float dd = Dv[c];

    const size_t base = ((size_t)b * SEQ) * N_IN + c;

    float xm2 = 0.0f, xm1 = 0.0f;
    if (t0 >= 2) {
        xm2 = xz[base + (size_t)(t0 - 2) * N_IN];
        xm1 = xz[base + (size_t)(t0 - 1) * N_IN];
    }

    float run = csum[((size_t)b * NCHUNK + chunk) * D_INNER + c];

    #pragma unroll 4
    for (int t = t0; t < t0 + CHUNK; t++) {
        float x0 = xz[base + (size_t)t * N_IN];
        float v = fmaf(w0, xm2, fmaf(w1, xm1, fmaf(w2, x0, cb)));
        float u = silu_f(v);
        run += u;
        float y = fmaf(run, bc, u * dd);
        float zz = xz[base + (size_t)t * N_IN + D_INNER];
        float out = y * silu_f(zz);
        yz[((size_t)b * SEQ + t) * D_INNER + c] = out;
        xm2 = xm1;
        xm1 = x0;
    }
}

// ---------------------------------------------------------------------------
// Launch
// ---------------------------------------------------------------------------
extern "C" void kernel_launch(void* const* d_in, const int* in_sizes, int n_in,
                              void* d_out, int out_size)
{
    const float* x      = (const float*)d_in[0];
    const float* W_in   = (const float*)d_in[1];
    const float* conv_w = (const float*)d_in[2];
    const float* conv_b = (const float*)d_in[3];
    const float* Bm     = (const float*)d_in[4];
    const float* Cm     = (const float*)d_in[5];
    const float* Dv     = (const float*)d_in[6];
    const float* W_out  = (const float*)d_in[7];
    float* out = (float*)d_out;

    float* xz;  cudaGetSymbolAddress((void**)&xz, g_XZ);
    float* yz;  cudaGetSymbolAddress((void**)&yz, g_YZ);
    float* cs;  cudaGetSymbolAddress((void**)&cs, g_CS);

    // GEMM1: xz = x @ W_in   [32768,768] x [768,1536]
    {
        dim3 grid(N_IN / BN, M_TOT / BM);
        sgemm_kernel<<<grid, 256>>>(x, W_in, xz, M_TOT, N_IN, D_MODEL);
    }
    // Scan pipeline
    {
        dim3 grid(NCHUNK, BATCH);
        scan_partial_kernel<<<grid, D_INNER>>>(xz, conv_w, conv_b, cs);
        scan_offsets_kernel<<<(BATCH * D_INNER + 255) / 256, 256>>>(cs);
        scan_apply_kernel<<<grid, D_INNER>>>(xz, conv_w, conv_b, Bm, Cm, Dv, cs, yz);
    }
    // GEMM2: out = yz @ W_out  [32768,768] x [768,768]
    {
        dim3 grid(D_MODEL / BN, M_TOT / BM);
        sgemm_kernel<<<grid, 256>>>(yz, W_out, out, M_TOT, D_MODEL, D_INNER);
    }
}

// round 5
// speedup vs baseline: 2.6995x; 2.6995x over previous
#include <cuda_runtime.h>
#include <cuda_bf16.h>
#include <cstdint>

// Problem constants
#define D_MODEL 768
#define D_INNER 768
#define D_STATE 8
#define D_CONV  3
#define BATCH   4
#define SEQ     8192
#define M_TOT   (BATCH * SEQ)        // 32768
#define N_IN    (2 * D_INNER)        // 1536
#define CHUNK   128
#define NCHUNK  (SEQ / CHUNK)        // 64

// Scratch (static __device__ arrays per allocation rules)
__device__ float g_Xr[(size_t)M_TOT * D_MODEL];          // tf32-rounded x
__device__ float g_XZ[(size_t)M_TOT * N_IN];             // x @ W_in (fp32 accum)
__device__ float g_YZ[(size_t)M_TOT * D_INNER];          // tf32-rounded y*silu(z)
__device__ float g_Wr[(size_t)D_MODEL * N_IN + (size_t)D_INNER * D_MODEL]; // rounded W_in | W_out
__device__ float g_CS[(size_t)BATCH * NCHUNK * D_INNER]; // chunk sums / offsets

// ---------------------------------------------------------------------------
// tf32 round-to-nearest helper
// ---------------------------------------------------------------------------
__device__ __forceinline__ float to_tf32(float x) {
    uint32_t r;
    asm("cvt.rna.tf32.f32 %0, %1;" : "=r"(r) : "f"(x));
    return __uint_as_float(r);
}

__global__ __launch_bounds__(256) void round_tf32_kernel(
    const float* __restrict__ in, float* __restrict__ out, int n4)
{
    int i = blockIdx.x * blockDim.x + threadIdx.x;
    if (i >= n4) return;
    float4 v = ((const float4*)in)[i];
    v.x = to_tf32(v.x); v.y = to_tf32(v.y); v.z = to_tf32(v.z); v.w = to_tf32(v.w);
    ((float4*)out)[i] = v;
}

// ---------------------------------------------------------------------------
// TF32 tensor-core GEMM: 128x128 blocktile, BK=16, cp.async double-buffered.
// 256 threads = 8 warps as 4(m) x 2(n); warp tile 32x64; mma.m16n8k8.tf32.
// A row-major [M,K], B row-major [K,N], C row-major [M,N]. Dims divide tiles.
// ---------------------------------------------------------------------------
#define BM 128
#define BN 128
#define BKT 16
#define ASTRIDE 20   // 16 + 4 pad: 80B row (16B-aligned), conflict-free frags
#define BSTRIDE 136  // 128 + 8 pad: 544B row (16B-aligned), conflict-free frags

__device__ __forceinline__ void mma_tf32(float* d, const uint32_t* a, const uint32_t* b) {
    asm volatile(
        "mma.sync.aligned.m16n8k8.row.col.f32.tf32.tf32.f32 "
        "{%0,%1,%2,%3}, {%4,%5,%6,%7}, {%8,%9}, {%0,%1,%2,%3};\n"
        : "+f"(d[0]), "+f"(d[1]), "+f"(d[2]), "+f"(d[3])
        : "r"(a[0]), "r"(a[1]), "r"(a[2]), "r"(a[3]), "r"(b[0]), "r"(b[1]));
}

__global__ __launch_bounds__(256) void gemm_tf32_kernel(
    const float* __restrict__ A, const float* __restrict__ B,
    float* __restrict__ C, int M, int N, int K)
{
    __shared__ float As[2][BM][ASTRIDE];
    __shared__ float Bs[2][BKT][BSTRIDE];

    const int tid  = threadIdx.x;
    const int lane = tid & 31;
    const int wid  = tid >> 5;
    const int wm   = wid >> 1;   // 0..3 -> m offset 32*wm
    const int wn   = wid & 1;    // 0..1 -> n offset 64*wn
    const int bm   = blockIdx.y;
    const int bn   = blockIdx.x;

    const float* Ab = A + (size_t)bm * BM * K;
    const float* Bb = B + (size_t)bn * BN;

    // cp.async addressing: A tile 128x16, B tile 16x128, 2 float4 per thread each
    const int ar = tid >> 2;          // 0..63 (+64)
    const int ac = (tid & 3) << 2;    // 0,4,8,12
    const int br = tid >> 5;          // 0..7  (+8)
    const int bc = (tid & 31) << 2;   // 0..124

    float acc[2][8][4];
    #pragma unroll
    for (int mi = 0; mi < 2; mi++)
        #pragma unroll
        for (int ni = 0; ni < 8; ni++)
            #pragma unroll
            for (int q = 0; q < 4; q++) acc[mi][ni][q] = 0.0f;

    const int NT = K / BKT;

    // prologue: tile 0 -> buf 0
    {
        #pragma unroll
        for (int p = 0; p < 2; p++) {
            unsigned d = (unsigned)__cvta_generic_to_shared(&As[0][ar + 64 * p][ac]);
            const float* s = Ab + (size_t)(ar + 64 * p) * K + ac;
            asm volatile("cp.async.cg.shared.global [%0], [%1], 16;" :: "r"(d), "l"(s));
        }
        #pragma unroll
        for (int p = 0; p < 2; p++) {
            unsigned d = (unsigned)__cvta_generic_to_shared(&Bs[0][br + 8 * p][bc]);
            const float* s = Bb + (size_t)(br + 8 * p) * N + bc;
            asm volatile("cp.async.cg.shared.global [%0], [%1], 16;" :: "r"(d), "l"(s));
        }
        asm volatile("cp.async.commit_group;");
    }

    for (int kt = 0; kt < NT; kt++) {
        const int buf = kt & 1;
        if (kt + 1 < NT) {
            const int nb = buf ^ 1;
            const int k0 = (kt + 1) * BKT;
            #pragma unroll
            for (int p = 0; p < 2; p++) {
                unsigned d = (unsigned)__cvta_generic_to_shared(&As[nb][ar + 64 * p][ac]);
                const float* s = Ab + (size_t)(ar + 64 * p) * K + k0 + ac;
                asm volatile("cp.async.cg.shared.global [%0], [%1], 16;" :: "r"(d), "l"(s));
            }
            #pragma unroll
            for (int p = 0; p < 2; p++) {
                unsigned d = (unsigned)__cvta_generic_to_shared(&Bs[nb][br + 8 * p][bc]);
                const float* s = Bb + (size_t)(k0 + br + 8 * p) * N + bc;
                asm volatile("cp.async.cg.shared.global [%0], [%1], 16;" :: "r"(d), "l"(s));
            }
            asm volatile("cp.async.commit_group;");
            asm volatile("cp.async.wait_group 1;");
        } else {
            asm volatile("cp.async.wait_group 0;");
        }
        __syncthreads();

        #pragma unroll
        for (int ks = 0; ks < BKT; ks += 8) {
            uint32_t afr[2][4];
            #pragma unroll
            for (int mi = 0; mi < 2; mi++) {
                const int r = wm * 32 + mi * 16 + (lane >> 2);
                const int c = ks + (lane & 3);
                afr[mi][0] = __float_as_uint(As[buf][r][c]);
                afr[mi][1] = __float_as_uint(As[buf][r + 8][c]);
                afr[mi][2] = __float_as_uint(As[buf][r][c + 4]);
                afr[mi][3] = __float_as_uint(As[buf][r + 8][c + 4]);
            }
            uint32_t bfr[8][2];
            #pragma unroll
            for (int ni = 0; ni < 8; ni++) {
                const int kk = ks + (lane & 3);
                const int n  = wn * 64 + ni * 8 + (lane >> 2);
                bfr[ni][0] = __float_as_uint(Bs[buf][kk][n]);
                bfr[ni][1] = __float_as_uint(Bs[buf][kk + 4][n]);
            }
            #pragma unroll
            for (int mi = 0; mi < 2; mi++)
                #pragma unroll
                for (int ni = 0; ni < 8; ni++)
                    mma_tf32(acc[mi][ni], afr[mi], bfr[ni]);
        }
        __syncthreads();
    }

    float* Cb = C + (size_t)bm * BM * N + (size_t)bn * BN;
    #pragma unroll
    for (int mi = 0; mi < 2; mi++) {
        #pragma unroll
        for (int ni = 0; ni < 8; ni++) {
            const int r = wm * 32 + mi * 16 + (lane >> 2);
            const int c = wn * 64 + ni * 8 + ((lane & 3) << 1);
            *(float2*)&Cb[(size_t)r * N + c] =
                make_float2(acc[mi][ni][0], acc[mi][ni][1]);
            *(float2*)&Cb[(size_t)(r + 8) * N + c] =
                make_float2(acc[mi][ni][2], acc[mi][ni][3]);
        }
    }
}

// ---------------------------------------------------------------------------
// silu helper
// ---------------------------------------------------------------------------
__device__ __forceinline__ float silu_f(float v) {
    return v / (1.0f + __expf(-v));
}

// ---------------------------------------------------------------------------
// Pass A: per-chunk sums of u = silu(conv3(xc) + bias)
// ---------------------------------------------------------------------------
__global__ __launch_bounds__(768) void scan_partial_kernel(
    const float* __restrict__ xz,
    const float* __restrict__ convw, const float* __restrict__ convb,
    float* __restrict__ csum)
{
    const int c = threadIdx.x;
    const int chunk = blockIdx.x;
    const int b = blockIdx.y;
    const int t0 = chunk * CHUNK;

    const float w0 = convw[c * 3 + 0];
    const float w1 = convw[c * 3 + 1];
    const float w2 = convw[c * 3 + 2];
    const float cb = convb[c];

    const size_t base = ((size_t)b * SEQ) * N_IN + c;

    float xm2 = 0.0f, xm1 = 0.0f;
    if (t0 >= 2) {
        xm2 = xz[base + (size_t)(t0 - 2) * N_IN];
        xm1 = xz[base + (size_t)(t0 - 1) * N_IN];
    }

    float s = 0.0f;
    #pragma unroll 4
    for (int t = t0; t < t0 + CHUNK; t++) {
        float x0 = xz[base + (size_t)t * N_IN];
        float v = fmaf(w0, xm2, fmaf(w1, xm1, fmaf(w2, x0, cb)));
        s += silu_f(v);
        xm2 = xm1;
        xm1 = x0;
    }
    csum[((size_t)b * NCHUNK + chunk) * D_INNER + c] = s;
}

// ---------------------------------------------------------------------------
// Pass B: in-place exclusive scan of chunk sums per (b,c)
// ---------------------------------------------------------------------------
__global__ __launch_bounds__(256) void scan_offsets_kernel(float* __restrict__ csum)
{
    const int idx = blockIdx.x * blockDim.x + threadIdx.x;
    if (idx >= BATCH * D_INNER) return;
    const int b = idx / D_INNER;
    const int c = idx % D_INNER;
    float run = 0.0f;
    for (int k = 0; k < NCHUNK; k++) {
        size_t p = ((size_t)b * NCHUNK + k) * D_INNER + c;
        float v = csum[p];
        csum[p] = run;
        run += v;
    }
}

// ---------------------------------------------------------------------------
// Pass C: recompute u, apply y = cum*BC + u*D, times silu(z); write tf32-rounded
// ---------------------------------------------------------------------------
__global__ __launch_bounds__(768) void scan_apply_kernel(
    const float* __restrict__ xz,
    const float* __restrict__ convw, const float* __restrict__ convb,
    const float* __restrict__ Bm, const float* __restrict__ Cm,
    const float* __restrict__ Dv,
    const float* __restrict__ csum,
    float* __restrict__ yz)
{
    const int c = threadIdx.x;
    const int chunk = blockIdx.x;
    const int b = blockIdx.y;
    const int t0 = chunk * CHUNK;

    const float w0 = convw[c * 3 + 0];
    const float w1 = convw[c * 3 + 1];
    const float w2 = convw[c * 3 + 2];
    const float cb = convb[c];

    float bc = 0.0f;
    #pragma unroll
    for (int s = 0; s < D_STATE; s++)
        bc = fmaf(Bm[c * D_STATE + s], Cm[c * D_STATE + s], bc);
    const float dd = Dv[c];

    const size_t base = ((size_t)b * SEQ) * N_IN + c;

    float xm2 = 0.0f, xm1 = 0.0f;
    if (t0 >= 2) {
        xm2 = xz[base + (size_t)(t0 - 2) * N_IN];
        xm1 = xz[base + (size_t)(t0 - 1) * N_IN];
    }

    float run = csum[((size_t)b * NCHUNK + chunk) * D_INNER + c];

    #pragma unroll 4
    for (int t = t0; t < t0 + CHUNK; t++) {
        float x0 = xz[base + (size_t)t * N_IN];
        float v = fmaf(w0, xm2, fmaf(w1, xm1, fmaf(w2, x0, cb)));
        float u = silu_f(v);
        run += u;
        float y = fmaf(run, bc, u * dd);
        float zz = xz[base + (size_t)t * N_IN + D_INNER];
        float out = y * silu_f(zz);
        yz[((size_t)b * SEQ + t) * D_INNER + c] = to_tf32(out);
        xm2 = xm1;
        xm1 = x0;
    }
}

// ---------------------------------------------------------------------------
// Launch
// ---------------------------------------------------------------------------
extern "C" void kernel_launch(void* const* d_in, const int* in_sizes, int n_in,
                              void* d_out, int out_size)
{
    const float* x      = (const float*)d_in[0];
    const float* W_in   = (const float*)d_in[1];
    const float* conv_w = (const float*)d_in[2];
    const float* conv_b = (const float*)d_in[3];
    const float* Bm     = (const float*)d_in[4];
    const float* Cm     = (const float*)d_in[5];
    const float* Dv     = (const float*)d_in[6];
    const float* W_out  = (const float*)d_in[7];
    float* out = (float*)d_out;

    float* xr;  cudaGetSymbolAddress((void**)&xr, g_Xr);
    float* xz;  cudaGetSymbolAddress((void**)&xz, g_XZ);
    float* yz;  cudaGetSymbolAddress((void**)&yz, g_YZ);
    float* wr;  cudaGetSymbolAddress((void**)&wr, g_Wr);
    float* cs;  cudaGetSymbolAddress((void**)&cs, g_CS);

    float* w_in_r  = wr;
    float* w_out_r = wr + (size_t)D_MODEL * N_IN;

    // tf32 round-to-nearest preprocessing
    {
        int n4 = (M_TOT * D_MODEL) / 4;
        round_tf32_kernel<<<(n4 + 255) / 256, 256>>>(x, xr, n4);
        n4 = (D_MODEL * N_IN) / 4;
        round_tf32_kernel<<<(n4 + 255) / 256, 256>>>(W_in, w_in_r, n4);
        n4 = (D_INNER * D_MODEL) / 4;
        round_tf32_kernel<<<(n4 + 255) / 256, 256>>>(W_out, w_out_r, n4);
    }

    // GEMM1: xz = xr @ W_in_r   [32768,768] x [768,1536]
    {
        dim3 grid(N_IN / BN, M_TOT / BM);
        gemm_tf32_kernel<<<grid, 256>>>(xr, w_in_r, xz, M_TOT, N_IN, D_MODEL);
    }
    // Scan pipeline
    {
        dim3 grid(NCHUNK, BATCH);
        scan_partial_kernel<<<grid, D_INNER>>>(xz, conv_w, conv_b, cs);
        scan_offsets_kernel<<<(BATCH * D_INNER + 255) / 256, 256>>>(cs);
        scan_apply_kernel<<<grid, D_INNER>>>(xz, conv_w, conv_b, Bm, Cm, Dv, cs, yz);
    }
    // GEMM2: out = yz @ W_out_r  [32768,768] x [768,768]
    {
        dim3 grid(D_MODEL / BN, M_TOT / BM);
        gemm_tf32_kernel<<<grid, 256>>>(yz, w_out_r, out, M_TOT, D_MODEL, D_INNER);
    }
}

// round 7
// speedup vs baseline: 2.9597x; 1.0964x over previous
#include <cuda_runtime.h>
#include <cuda_bf16.h>
#include <cstdint>

// Problem constants
#define D_MODEL 768
#define D_INNER 768
#define D_STATE 8
#define BATCH   4
#define SEQ     8192
#define M_TOT   (BATCH * SEQ)        // 32768
#define N_IN    (2 * D_INNER)        // 1536
#define KDIM    768
#define CHUNK   64
#define NCHUNK  (SEQ / CHUNK)        // 128

// Scratch (static __device__ arrays per allocation rules)
__device__ float g_XZ[(size_t)M_TOT * N_IN];             // x @ W_in (fp32)
__device__ float g_YZ[(size_t)M_TOT * D_INNER];          // tf32-rounded y*silu(z)
__device__ float g_Wr[(size_t)D_MODEL * N_IN + (size_t)D_INNER * D_MODEL]; // rounded W_in | W_out
__device__ float g_CS[(size_t)BATCH * NCHUNK * D_INNER]; // chunk sums / offsets

// ---------------------------------------------------------------------------
// tf32 helpers
// ---------------------------------------------------------------------------
__device__ __forceinline__ float to_tf32(float x) {
    uint32_t r;
    asm("cvt.rna.tf32.f32 %0, %1;" : "=r"(r) : "f"(x));
    return __uint_as_float(r);
}
__device__ __forceinline__ uint32_t tf32_bits(float x) {
    uint32_t r;
    asm("cvt.rna.tf32.f32 %0, %1;" : "=r"(r) : "f"(x));
    return r;
}

__global__ __launch_bounds__(256) void round_tf32_kernel(
    const float* __restrict__ in, float* __restrict__ out, int n4)
{
    int i = blockIdx.x * blockDim.x + threadIdx.x;
    if (i >= n4) return;
    float4 v = ((const float4*)in)[i];
    v.x = to_tf32(v.x); v.y = to_tf32(v.y); v.z = to_tf32(v.z); v.w = to_tf32(v.w);
    ((float4*)out)[i] = v;
}

// ---------------------------------------------------------------------------
// TF32 tensor-core GEMM: 128x128 blocktile, BK=16, 3-stage cp.async ring.
// 256 threads = 8 warps as 4(m) x 2(n); warp tile 32x64; mma.m16n8k8.tf32.
// ROUND_A: cvt.rna.tf32 applied to A fragments in registers (A may be raw fp32).
// B must be pre-rounded. A row-major [M,K], B row-major [K,N], C row-major.
// ---------------------------------------------------------------------------
#define BM 128
#define BN 128
#define BKT 16
#define STAGES 3
#define ASTRIDE 20   // 16 + 4 pad
#define BSTRIDE 136  // 128 + 8 pad
#define A_STAGE_F (BM * ASTRIDE)            // 2560 floats
#define B_STAGE_F (BKT * BSTRIDE)           // 2176 floats
#define GEMM_SMEM_BYTES ((STAGES * (A_STAGE_F + B_STAGE_F)) * 4)  // 56832

__device__ __forceinline__ void mma_tf32(float* d, const uint32_t* a, const uint32_t* b) {
    asm volatile(
        "mma.sync.aligned.m16n8k8.row.col.f32.tf32.tf32.f32 "
        "{%0,%1,%2,%3}, {%4,%5,%6,%7}, {%8,%9}, {%0,%1,%2,%3};\n"
        : "+f"(d[0]), "+f"(d[1]), "+f"(d[2]), "+f"(d[3])
        : "r"(a[0]), "r"(a[1]), "r"(a[2]), "r"(a[3]), "r"(b[0]), "r"(b[1]));
}

__device__ __forceinline__ void cpa16(void* dst, const void* src) {
    unsigned d = (unsigned)__cvta_generic_to_shared(dst);
    asm volatile("cp.async.cg.shared.global [%0], [%1], 16;" :: "r"(d), "l"(src) : "memory");
}

template<bool ROUND_A>
__global__ __launch_bounds__(256, 2) void gemm_tf32_kernel(
    const float* __restrict__ A, const float* __restrict__ B,
    float* __restrict__ C, int M, int N, int K)
{
    extern __shared__ float smem[];
    float* Asm = smem;                          // [STAGES][BM][ASTRIDE]
    float* Bsm = smem + STAGES * A_STAGE_F;     // [STAGES][BKT][BSTRIDE]

    const int tid  = threadIdx.x;
    const int lane = tid & 31;
    const int wid  = tid >> 5;
    const int wm   = wid >> 1;   // 0..3
    const int wn   = wid & 1;    // 0..1
    const int bm   = blockIdx.y;
    const int bn   = blockIdx.x;

    const float* Ab = A + (size_t)bm * BM * K;
    const float* Bb = B + (size_t)bn * BN;

    const int ar = tid >> 2;          // 0..63 (+64)
    const int ac = (tid & 3) << 2;    // 0,4,8,12
    const int br = tid >> 5;          // 0..7  (+8)
    const int bc = (tid & 31) << 2;   // 0..124

    float acc[2][8][4];
    #pragma unroll
    for (int mi = 0; mi < 2; mi++)
        #pragma unroll
        for (int ni = 0; ni < 8; ni++)
            #pragma unroll
            for (int q = 0; q < 4; q++) acc[mi][ni][q] = 0.0f;

    const int NT = K / BKT;

    auto load_stage = [&](int kt, int st) {
        float* As = Asm + st * A_STAGE_F;
        float* Bs = Bsm + st * B_STAGE_F;
        const int k0 = kt * BKT;
        #pragma unroll
        for (int p = 0; p < 2; p++)
            cpa16(&As[(ar + 64 * p) * ASTRIDE + ac],
                  Ab + (size_t)(ar + 64 * p) * K + k0 + ac);
        #pragma unroll
        for (int p = 0; p < 2; p++)
            cpa16(&Bs[(br + 8 * p) * BSTRIDE + bc],
                  Bb + (size_t)(k0 + br + 8 * p) * N + bc);
        asm volatile("cp.async.commit_group;" ::: "memory");
    };

    // prologue: stages 0,1
    load_stage(0, 0);
    load_stage(1, 1);

    for (int kt = 0; kt < NT; kt++) {
        if (kt + 2 < NT) {
            asm volatile("cp.async.wait_group 1;" ::: "memory");
        } else {
            asm volatile("cp.async.wait_group 0;" ::: "memory");
        }
        __syncthreads();

        // issue next stage load (buffer (kt+2)%3 was consumed at kt-1)
        if (kt + 2 < NT) load_stage(kt + 2, (kt + 2) % STAGES);

        const float* As = Asm + (kt % STAGES) * A_STAGE_F;
        const float* Bs = Bsm + (kt % STAGES) * B_STAGE_F;

        #pragma unroll
        for (int ks = 0; ks < BKT; ks += 8) {
            uint32_t afr[2][4];
            #pragma unroll
            for (int mi = 0; mi < 2; mi++) {
                const int r = wm * 32 + mi * 16 + (lane >> 2);
                const int c = ks + (lane & 3);
                float a0 = As[r * ASTRIDE + c];
                float a1 = As[(r + 8) * ASTRIDE + c];
                float a2 = As[r * ASTRIDE + c + 4];
                float a3 = As[(r + 8) * ASTRIDE + c + 4];
                if (ROUND_A) {
                    afr[mi][0] = tf32_bits(a0); afr[mi][1] = tf32_bits(a1);
                    afr[mi][2] = tf32_bits(a2); afr[mi][3] = tf32_bits(a3);
                } else {
                    afr[mi][0] = __float_as_uint(a0); afr[mi][1] = __float_as_uint(a1);
                    afr[mi][2] = __float_as_uint(a2); afr[mi][3] = __float_as_uint(a3);
                }
            }
            uint32_t bfr[8][2];
            #pragma unroll
            for (int ni = 0; ni < 8; ni++) {
                const int kk = ks + (lane & 3);
                const int n  = wn * 64 + ni * 8 + (lane >> 2);
                bfr[ni][0] = __float_as_uint(Bs[kk * BSTRIDE + n]);
                bfr[ni][1] = __float_as_uint(Bs[(kk + 4) * BSTRIDE + n]);
            }
            #pragma unroll
            for (int mi = 0; mi < 2; mi++)
                #pragma unroll
                for (int ni = 0; ni < 8; ni++)
                    mma_tf32(acc[mi][ni], afr[mi], bfr[ni]);
        }
        __syncthreads();
    }

    float* Cb = C + (size_t)bm * BM * N + (size_t)bn * BN;
    #pragma unroll
    for (int mi = 0; mi < 2; mi++) {
        #pragma unroll
        for (int ni = 0; ni < 8; ni++) {
            const int r = wm * 32 + mi * 16 + (lane >> 2);
            const int c = wn * 64 + ni * 8 + ((lane & 3) << 1);
            *(float2*)&Cb[(size_t)r * N + c] =
                make_float2(acc[mi][ni][0], acc[mi][ni][1]);
            *(float2*)&Cb[(size_t)(r + 8) * N + c] =
                make_float2(acc[mi][ni][2], acc[mi][ni][3]);
        }
    }
}

// ---------------------------------------------------------------------------
// silu helper
// ---------------------------------------------------------------------------
__device__ __forceinline__ float silu_f(float v) {
    return v / (1.0f + __expf(-v));
}

// ---------------------------------------------------------------------------
// Pass A: per-chunk sums of u = silu(conv3(xc)+bias). 4 channels per thread.
// Block = 192 threads, grid = (NCHUNK, BATCH).
// ---------------------------------------------------------------------------
__global__ __launch_bounds__(192) void scan_partial_kernel(
    const float* __restrict__ xz,
    const float* __restrict__ convw, const float* __restrict__ convb,
    float* __restrict__ csum)
{
    const int tq = threadIdx.x;           // channels 4tq..4tq+3
    const int chunk = blockIdx.x;
    const int b = blockIdx.y;
    const int t0 = chunk * CHUNK;
    const int c0 = tq * 4;

    float w0[4], w1[4], w2[4], cb[4];
    #pragma unroll
    for (int j = 0; j < 4; j++) {
        w0[j] = convw[(c0 + j) * 3 + 0];
        w1[j] = convw[(c0 + j) * 3 + 1];
        w2[j] = convw[(c0 + j) * 3 + 2];
        cb[j] = convb[c0 + j];
    }

    const float* p = xz + ((size_t)b * SEQ + t0) * N_IN + c0;

    float4 xm2 = make_float4(0, 0, 0, 0), xm1 = make_float4(0, 0, 0, 0);
    if (t0 >= 2) {
        xm2 = *(const float4*)(p - 2 * N_IN);
        xm1 = *(const float4*)(p - 1 * N_IN);
    }

    float s[4] = {0, 0, 0, 0};
    #pragma unroll 4
    for (int t = 0; t < CHUNK; t++) {
        float4 x0 = *(const float4*)(p + (size_t)t * N_IN);
        float m2[4] = {xm2.x, xm2.y, xm2.z, xm2.w};
        float m1[4] = {xm1.x, xm1.y, xm1.z, xm1.w};
        float cc[4] = {x0.x, x0.y, x0.z, x0.w};
        #pragma unroll
        for (int j = 0; j < 4; j++) {
            float v = fmaf(w0[j], m2[j], fmaf(w1[j], m1[j], fmaf(w2[j], cc[j], cb[j])));
            s[j] += silu_f(v);
        }
        xm2 = xm1; xm1 = x0;
    }
    *(float4*)&csum[((size_t)b * NCHUNK + chunk) * D_INNER + c0] =
        make_float4(s[0], s[1], s[2], s[3]);
}

// ---------------------------------------------------------------------------
// Pass B: in-place exclusive scan of chunk sums per (b, 4-channel group)
// ---------------------------------------------------------------------------
__global__ __launch_bounds__(256) void scan_offsets_kernel(float* __restrict__ csum)
{
    const int idx = blockIdx.x * blockDim.x + threadIdx.x;   // 0..767
    if (idx >= BATCH * (D_INNER / 4)) return;
    const int b = idx / (D_INNER / 4);
    const int c0 = (idx % (D_INNER / 4)) * 4;
    float4 run = make_float4(0, 0, 0, 0);
    for (int k = 0; k < NCHUNK; k++) {
        float4* p = (float4*)&csum[((size_t)b * NCHUNK + k) * D_INNER + c0];
        float4 v = *p;
        *p = run;
        run.x += v.x; run.y += v.y; run.z += v.z; run.w += v.w;
    }
}

// ---------------------------------------------------------------------------
// Pass C: recompute u, y = cum*BC + u*D, times silu(z); write tf32-rounded.
// 4 channels per thread.
// ---------------------------------------------------------------------------
__global__ __launch_bounds__(192) void scan_apply_kernel(
    const float* __restrict__ xz,
    const float* __restrict__ convw, const float* __restrict__ convb,
    const float* __restrict__ Bm, const float* __restrict__ Cm,
    const float* __restrict__ Dv,
    const float* __restrict__ csum,
    float* __restrict__ yz)
{
    const int tq = threadIdx.x;
    const int chunk = blockIdx.x;
    const int b = blockIdx.y;
    const int t0 = chunk * CHUNK;
    const int c0 = tq * 4;

    float w0[4], w1[4], w2[4], cb[4], bc[4], dd[4];
    #pragma unroll
    for (int j = 0; j < 4; j++) {
        w0[j] = convw[(c0 + j) * 3 + 0];
        w1[j] = convw[(c0 + j) * 3 + 1];
        w2[j] = convw[(c0 + j) * 3 + 2];
        cb[j] = convb[c0 + j];
        float acc = 0.0f;
        #pragma unroll
        for (int s = 0; s < D_STATE; s++)
            acc = fmaf(Bm[(c0 + j) * D_STATE + s], Cm[(c0 + j) * D_STATE + s], acc);
        bc[j] = acc;
        dd[j] = Dv[c0 + j];
    }

    const float* p = xz + ((size_t)b * SEQ + t0) * N_IN + c0;
    float* q = yz + ((size_t)b * SEQ + t0) * D_INNER + c0;

    float4 xm2 = make_float4(0, 0, 0, 0), xm1 = make_float4(0, 0, 0, 0);
    if (t0 >= 2) {
        xm2 = *(const float4*)(p - 2 * N_IN);
        xm1 = *(const float4*)(p - 1 * N_IN);
    }

    float4 runv = *(const float4*)&csum[((size_t)b * NCHUNK + chunk) * D_INNER + c0];
    float run[4] = {runv.x, runv.y, runv.z, runv.w};

    #pragma unroll 4
    for (int t = 0; t < CHUNK; t++) {
        float4 x0 = *(const float4*)(p + (size_t)t * N_IN);
        float4 zz = *(const float4*)(p + (size_t)t * N_IN + D_INNER);
        float m2[4] = {xm2.x, xm2.y, xm2.z, xm2.w};
        float m1[4] = {xm1.x, xm1.y, xm1.z, xm1.w};
        float cc[4] = {x0.x, x0.y, x0.z, x0.w};
        float zv[4] = {zz.x, zz.y, zz.z, zz.w};
        float o[4];
        #pragma unroll
        for (int j = 0; j < 4; j++) {
            float v = fmaf(w0[j], m2[j], fmaf(w1[j], m1[j], fmaf(w2[j], cc[j], cb[j])));
            float u = silu_f(v);
            run[j] += u;
            float y = fmaf(run[j], bc[j], u * dd[j]);
            o[j] = to_tf32(y * silu_f(zv[j]));
        }
        *(float4*)(q + (size_t)t * D_INNER) = make_float4(o[0], o[1], o[2], o[3]);
        xm2 = xm1; xm1 = x0;
    }
}

// ---------------------------------------------------------------------------
// Launch
// ---------------------------------------------------------------------------
extern "C" void kernel_launch(void* const* d_in, const int* in_sizes, int n_in,
                              void* d_out, int out_size)
{
    const float* x      = (const float*)d_in[0];
    const float* W_in   = (const float*)d_in[1];
    const float* conv_w = (const float*)d_in[2];
    const float* conv_b = (const float*)d_in[3];
    const float* Bm     = (const float*)d_in[4];
    const float* Cm     = (const float*)d_in[5];
    const float* Dv     = (const float*)d_in[6];
    const float* W_out  = (const float*)d_in[7];
    float* out = (float*)d_out;

    float* xz;  cudaGetSymbolAddress((void**)&xz, g_XZ);
    float* yz;  cudaGetSymbolAddress((void**)&yz, g_YZ);
    float* wr;  cudaGetSymbolAddress((void**)&wr, g_Wr);
    float* cs;  cudaGetSymbolAddress((void**)&cs, g_CS);

    float* w_in_r  = wr;
    float* w_out_r = wr + (size_t)D_MODEL * N_IN;

    static bool attr_done = false;
    if (!attr_done) {
        cudaFuncSetAttribute(gemm_tf32_kernel<true>,
                             cudaFuncAttributeMaxDynamicSharedMemorySize, GEMM_SMEM_BYTES);
        cudaFuncSetAttribute(gemm_tf32_kernel<false>,
                             cudaFuncAttributeMaxDynamicSharedMemorySize, GEMM_SMEM_BYTES);
        attr_done = true;
    }

    // Pre-round weights only (x is rounded in-register inside GEMM1)
    {
        int n4 = (D_MODEL * N_IN) / 4;
        round_tf32_kernel<<<(n4 + 255) / 256, 256>>>(W_in, w_in_r, n4);
        n4 = (D_INNER * D_MODEL) / 4;
        round_tf32_kernel<<<(n4 + 255) / 256, 256>>>(W_out, w_out_r, n4);
    }

    // GEMM1: xz = round(x) @ W_in_r   [32768,768] x [768,1536]
    {
        dim3 grid(N_IN / BN, M_TOT / BM);
        gemm_tf32_kernel<true><<<grid, 256, GEMM_SMEM_BYTES>>>(
            x, w_in_r, xz, M_TOT, N_IN, D_MODEL);
    }
    // Scan pipeline
    {
        dim3 grid(NCHUNK, BATCH);
        scan_partial_kernel<<<grid, 192>>>(xz, conv_w, conv_b, cs);
        scan_offsets_kernel<<<3, 256>>>(cs);
        scan_apply_kernel<<<grid, 192>>>(xz, conv_w, conv_b, Bm, Cm, Dv, cs, yz);
    }
    // GEMM2: out = yz @ W_out_r  [32768,768] x [768,768]
    {
        dim3 grid(D_MODEL / BN, M_TOT / BM);
        gemm_tf32_kernel<false><<<grid, 256, GEMM_SMEM_BYTES>>>(
            yz, w_out_r, out, M_TOT, D_MODEL, D_INNER);
    }
}

// round 8
// speedup vs baseline: 3.2255x; 1.0898x over previous
#include <cuda_runtime.h>
#include <cuda_bf16.h>
#include <cstdint>

// Problem constants
#define D_MODEL 768
#define D_INNER 768
#define D_STATE 8
#define BATCH   4
#define SEQ     8192
#define M_TOT   (BATCH * SEQ)        // 32768
#define N_IN    (2 * D_INNER)        // 1536
#define KDIM    768
#define CHUNK   32
#define NCHUNK  (SEQ / CHUNK)        // 256

// Scratch (static __device__ arrays per allocation rules)
__device__ float g_XZ[(size_t)M_TOT * N_IN];             // x @ W_in (fp32)
__device__ float g_YZ[(size_t)M_TOT * D_INNER];          // tf32-rounded y*silu(z)
__device__ float g_Wr[(size_t)D_MODEL * N_IN + (size_t)D_INNER * D_MODEL]; // rounded W_in | W_out
__device__ float g_CS[(size_t)BATCH * NCHUNK * D_INNER]; // chunk sums / offsets

// ---------------------------------------------------------------------------
// tf32 helpers
// ---------------------------------------------------------------------------
__device__ __forceinline__ float to_tf32(float x) {
    uint32_t r;
    asm("cvt.rna.tf32.f32 %0, %1;" : "=r"(r) : "f"(x));
    return __uint_as_float(r);
}
__device__ __forceinline__ uint32_t tf32_bits(float x) {
    uint32_t r;
    asm("cvt.rna.tf32.f32 %0, %1;" : "=r"(r) : "f"(x));
    return r;
}

__global__ __launch_bounds__(256) void round_tf32_kernel(
    const float* __restrict__ in, float* __restrict__ out, int n4)
{
    int i = blockIdx.x * blockDim.x + threadIdx.x;
    if (i >= n4) return;
    float4 v = ((const float4*)in)[i];
    v.x = to_tf32(v.x); v.y = to_tf32(v.y); v.z = to_tf32(v.z); v.w = to_tf32(v.w);
    ((float4*)out)[i] = v;
}

// ---------------------------------------------------------------------------
// TF32 tensor-core GEMM: 128x128 blocktile, BK=32, 3-stage cp.async ring,
// one barrier per K-iteration. 256 threads = 8 warps (4m x 2n), warp tile
// 32x64, mma.m16n8k8.tf32. ROUND_A rounds A frags in registers.
// ---------------------------------------------------------------------------
#define BM 128
#define BN 128
#define BKT 32
#define STAGES 3
#define ASTRIDE 36   // 32 + 4 pad
#define BSTRIDE 136  // 128 + 8 pad
#define A_STAGE_F (BM * ASTRIDE)            // 4608 floats
#define B_STAGE_F (BKT * BSTRIDE)           // 4352 floats
#define GEMM_SMEM_BYTES ((STAGES * (A_STAGE_F + B_STAGE_F)) * 4)  // 107520

__device__ __forceinline__ void mma_tf32(float* d, const uint32_t* a, const uint32_t* b) {
    asm volatile(
        "mma.sync.aligned.m16n8k8.row.col.f32.tf32.tf32.f32 "
        "{%0,%1,%2,%3}, {%4,%5,%6,%7}, {%8,%9}, {%0,%1,%2,%3};\n"
        : "+f"(d[0]), "+f"(d[1]), "+f"(d[2]), "+f"(d[3])
        : "r"(a[0]), "r"(a[1]), "r"(a[2]), "r"(a[3]), "r"(b[0]), "r"(b[1]));
}

__device__ __forceinline__ void cpa16(void* dst, const void* src) {
    unsigned d = (unsigned)__cvta_generic_to_shared(dst);
    asm volatile("cp.async.cg.shared.global [%0], [%1], 16;" :: "r"(d), "l"(src) : "memory");
}

template<bool ROUND_A>
__global__ __launch_bounds__(256, 2) void gemm_tf32_kernel(
    const float* __restrict__ A, const float* __restrict__ B,
    float* __restrict__ C, int M, int N, int K)
{
    extern __shared__ float smem[];
    float* Asm = smem;                          // [STAGES][BM][ASTRIDE]
    float* Bsm = smem + STAGES * A_STAGE_F;     // [STAGES][BKT][BSTRIDE]

    const int tid  = threadIdx.x;
    const int lane = tid & 31;
    const int wid  = tid >> 5;
    const int wm   = wid >> 1;   // 0..3
    const int wn   = wid & 1;    // 0..1
    const int bm   = blockIdx.y;
    const int bn   = blockIdx.x;

    const float* Ab = A + (size_t)bm * BM * K;
    const float* Bb = B + (size_t)bn * BN;

    float acc[2][8][4];
    #pragma unroll
    for (int mi = 0; mi < 2; mi++)
        #pragma unroll
        for (int ni = 0; ni < 8; ni++)
            #pragma unroll
            for (int q = 0; q < 4; q++) acc[mi][ni][q] = 0.0f;

    const int NT = K / BKT;   // 24

    auto load_stage = [&](int kt, int st) {
        float* As = Asm + st * A_STAGE_F;
        float* Bs = Bsm + st * B_STAGE_F;
        const int k0 = kt * BKT;
        // A tile 128x32 floats = 1024 float4
        #pragma unroll
        for (int i = 0; i < 4; i++) {
            const int idx = tid + i * 256;
            const int r = idx >> 3, c4 = (idx & 7) << 2;
            cpa16(&As[r * ASTRIDE + c4], Ab + (size_t)r * K + k0 + c4);
        }
        // B tile 32x128 floats = 1024 float4
        #pragma unroll
        for (int i = 0; i < 4; i++) {
            const int idx = tid + i * 256;
            const int r = idx >> 5, c4 = (idx & 31) << 2;
            cpa16(&Bs[r * BSTRIDE + c4], Bb + (size_t)(k0 + r) * N + c4);
        }
        asm volatile("cp.async.commit_group;" ::: "memory");
    };

    load_stage(0, 0);
    load_stage(1, 1);

    for (int kt = 0; kt < NT; kt++) {
        if (kt + 2 < NT) {
            asm volatile("cp.async.wait_group 1;" ::: "memory");
        } else {
            asm volatile("cp.async.wait_group 0;" ::: "memory");
        }
        __syncthreads();   // single barrier per iteration

        if (kt + 2 < NT) load_stage(kt + 2, (kt + 2) % STAGES);

        const float* As = Asm + (kt % STAGES) * A_STAGE_F;
        const float* Bs = Bsm + (kt % STAGES) * B_STAGE_F;

        #pragma unroll
        for (int ks = 0; ks < BKT; ks += 8) {
            uint32_t afr[2][4];
            #pragma unroll
            for (int mi = 0; mi < 2; mi++) {
                const int r = wm * 32 + mi * 16 + (lane >> 2);
                const int c = ks + (lane & 3);
                float a0 = As[r * ASTRIDE + c];
                float a1 = As[(r + 8) * ASTRIDE + c];
                float a2 = As[r * ASTRIDE + c + 4];
                float a3 = As[(r + 8) * ASTRIDE + c + 4];
                if (ROUND_A) {
                    afr[mi][0] = tf32_bits(a0); afr[mi][1] = tf32_bits(a1);
                    afr[mi][2] = tf32_bits(a2); afr[mi][3] = tf32_bits(a3);
                } else {
                    afr[mi][0] = __float_as_uint(a0); afr[mi][1] = __float_as_uint(a1);
                    afr[mi][2] = __float_as_uint(a2); afr[mi][3] = __float_as_uint(a3);
                }
            }
            uint32_t bfr[8][2];
            #pragma unroll
            for (int ni = 0; ni < 8; ni++) {
                const int kk = ks + (lane & 3);
                const int n  = wn * 64 + ni * 8 + (lane >> 2);
                bfr[ni][0] = __float_as_uint(Bs[kk * BSTRIDE + n]);
                bfr[ni][1] = __float_as_uint(Bs[(kk + 4) * BSTRIDE + n]);
            }
            #pragma unroll
            for (int mi = 0; mi < 2; mi++)
                #pragma unroll
                for (int ni = 0; ni < 8; ni++)
                    mma_tf32(acc[mi][ni], afr[mi], bfr[ni]);
        }
    }

    float* Cb = C + (size_t)bm * BM * N + (size_t)bn * BN;
    #pragma unroll
    for (int mi = 0; mi < 2; mi++) {
        #pragma unroll
        for (int ni = 0; ni < 8; ni++) {
            const int r = wm * 32 + mi * 16 + (lane >> 2);
            const int c = wn * 64 + ni * 8 + ((lane & 3) << 1);
            *(float2*)&Cb[(size_t)r * N + c] =
                make_float2(acc[mi][ni][0], acc[mi][ni][1]);
            *(float2*)&Cb[(size_t)(r + 8) * N + c] =
                make_float2(acc[mi][ni][2], acc[mi][ni][3]);
        }
    }
}

// ---------------------------------------------------------------------------
// silu helper
// ---------------------------------------------------------------------------
__device__ __forceinline__ float silu_f(float v) {
    return v / (1.0f + __expf(-v));
}

// ---------------------------------------------------------------------------
// Pass A: per-chunk sums of u = silu(conv3(xc)+bias). 4 channels per thread.
// Block = 192 threads, grid = (NCHUNK, BATCH).
// ---------------------------------------------------------------------------
__global__ __launch_bounds__(192) void scan_partial_kernel(
    const float* __restrict__ xz,
    const float* __restrict__ convw, const float* __restrict__ convb,
    float* __restrict__ csum)
{
    const int tq = threadIdx.x;
    const int chunk = blockIdx.x;
    const int b = blockIdx.y;
    const int t0 = chunk * CHUNK;
    const int c0 = tq * 4;

    float w0[4], w1[4], w2[4], cb[4];
    #pragma unroll
    for (int j = 0; j < 4; j++) {
        w0[j] = convw[(c0 + j) * 3 + 0];
        w1[j] = convw[(c0 + j) * 3 + 1];
        w2[j] = convw[(c0 + j) * 3 + 2];
        cb[j] = convb[c0 + j];
    }

    const float* p = xz + ((size_t)b * SEQ + t0) * N_IN + c0;

    float4 xm2 = make_float4(0, 0, 0, 0), xm1 = make_float4(0, 0, 0, 0);
    if (t0 >= 2) {
        xm2 = *(const float4*)(p - 2 * N_IN);
        xm1 = *(const float4*)(p - 1 * N_IN);
    }

    float s[4] = {0, 0, 0, 0};
    #pragma unroll 4
    for (int t = 0; t < CHUNK; t++) {
        float4 x0 = *(const float4*)(p + (size_t)t * N_IN);
        float m2[4] = {xm2.x, xm2.y, xm2.z, xm2.w};
        float m1[4] = {xm1.x, xm1.y, xm1.z, xm1.w};
        float cc[4] = {x0.x, x0.y, x0.z, x0.w};
        #pragma unroll
        for (int j = 0; j < 4; j++) {
            float v = fmaf(w0[j], m2[j], fmaf(w1[j], m1[j], fmaf(w2[j], cc[j], cb[j])));
            s[j] += silu_f(v);
        }
        xm2 = xm1; xm1 = x0;
    }
    *(float4*)&csum[((size_t)b * NCHUNK + chunk) * D_INNER + c0] =
        make_float4(s[0], s[1], s[2], s[3]);
}

// ---------------------------------------------------------------------------
// Pass B: block-parallel exclusive scan over NCHUNK chunk sums.
// Grid = (D_INNER/4, BATCH), block = NCHUNK threads. Hillis-Steele in smem.
// ---------------------------------------------------------------------------
__global__ __launch_bounds__(NCHUNK) void scan_offsets_kernel(float* __restrict__ csum)
{
    __shared__ float4 sh[NCHUNK];
    const int k = threadIdx.x;
    const int c0 = blockIdx.x * 4;
    const int b = blockIdx.y;

    float4* ptr = (float4*)&csum[((size_t)b * NCHUNK + k) * D_INNER + c0];
    float4 v = *ptr;
    sh[k] = v;
    __syncthreads();

    #pragma unroll
    for (int off = 1; off < NCHUNK; off <<= 1) {
        float4 t = make_float4(0, 0, 0, 0);
        const bool has = (k >= off);
        if (has) t = sh[k - off];
        __syncthreads();
        if (has) {
            v.x += t.x; v.y += t.y; v.z += t.z; v.w += t.w;
            sh[k] = v;
        }
        __syncthreads();
    }
    // exclusive = inclusive shifted right by one
    float4 ex = (k > 0) ? sh[k - 1] : make_float4(0, 0, 0, 0);
    *ptr = ex;
}

// ---------------------------------------------------------------------------
// Pass C: recompute u, y = cum*BC + u*D, times silu(z); write tf32-rounded.
// ---------------------------------------------------------------------------
__global__ __launch_bounds__(192) void scan_apply_kernel(
    const float* __restrict__ xz,
    const float* __restrict__ convw, const float* __restrict__ convb,
    const float* __restrict__ Bm, const float* __restrict__ Cm,
    const float* __restrict__ Dv,
    const float* __restrict__ csum,
    float* __restrict__ yz)
{
    const int tq = threadIdx.x;
    const int chunk = blockIdx.x;
    const int b = blockIdx.y;
    const int t0 = chunk * CHUNK;
    const int c0 = tq * 4;

    float w0[4], w1[4], w2[4], cb[4], bc[4], dd[4];
    #pragma unroll
    for (int j = 0; j < 4; j++) {
        w0[j] = convw[(c0 + j) * 3 + 0];
        w1[j] = convw[(c0 + j) * 3 + 1];
        w2[j] = convw[(c0 + j) * 3 + 2];
        cb[j] = convb[c0 + j];
        float acc = 0.0f;
        #pragma unroll
        for (int s = 0; s < D_STATE; s++)
            acc = fmaf(Bm[(c0 + j) * D_STATE + s], Cm[(c0 + j) * D_STATE + s], acc);
        bc[j] = acc;
        dd[j] = Dv[c0 + j];
    }

    const float* p = xz + ((size_t)b * SEQ + t0) * N_IN + c0;
    float* q = yz + ((size_t)b * SEQ + t0) * D_INNER + c0;

    float4 xm2 = make_float4(0, 0, 0, 0), xm1 = make_float4(0, 0, 0, 0);
    if (t0 >= 2) {
        xm2 = *(const float4*)(p - 2 * N_IN);
        xm1 = *(const float4*)(p - 1 * N_IN);
    }

    float4 runv = *(const float4*)&csum[((size_t)b * NCHUNK + chunk) * D_INNER + c0];
    float run[4] = {runv.x, runv.y, runv.z, runv.w};

    #pragma unroll 4
    for (int t = 0; t < CHUNK; t++) {
        float4 x0 = *(const float4*)(p + (size_t)t * N_IN);
        float4 zz = *(const float4*)(p + (size_t)t * N_IN + D_INNER);
        float m2[4] = {xm2.x, xm2.y, xm2.z, xm2.w};
        float m1[4] = {xm1.x, xm1.y, xm1.z, xm1.w};
        float cc[4] = {x0.x, x0.y, x0.z, x0.w};
        float zv[4] = {zz.x, zz.y, zz.z, zz.w};
        float o[4];
        #pragma unroll
        for (int j = 0; j < 4; j++) {
            float v = fmaf(w0[j], m2[j], fmaf(w1[j], m1[j], fmaf(w2[j], cc[j], cb[j])));
            float u = silu_f(v);
            run[j] += u;
            float y = fmaf(run[j], bc[j], u * dd[j]);
            o[j] = to_tf32(y * silu_f(zv[j]));
        }
        *(float4*)(q + (size_t)t * D_INNER) = make_float4(o[0], o[1], o[2], o[3]);
        xm2 = xm1; xm1 = x0;
    }
}

// ---------------------------------------------------------------------------
// Launch
// ---------------------------------------------------------------------------
extern "C" void kernel_launch(void* const* d_in, const int* in_sizes, int n_in,
                              void* d_out, int out_size)
{
    const float* x      = (const float*)d_in[0];
    const float* W_in   = (const float*)d_in[1];
    const float* conv_w = (const float*)d_in[2];
    const float* conv_b = (const float*)d_in[3];
    const float* Bm     = (const float*)d_in[4];
    const float* Cm     = (const float*)d_in[5];
    const float* Dv     = (const float*)d_in[6];
    const float* W_out  = (const float*)d_in[7];
    float* out = (float*)d_out;

    float* xz;  cudaGetSymbolAddress((void**)&xz, g_XZ);
    float* yz;  cudaGetSymbolAddress((void**)&yz, g_YZ);
    float* wr;  cudaGetSymbolAddress((void**)&wr, g_Wr);
    float* cs;  cudaGetSymbolAddress((void**)&cs, g_CS);

    float* w_in_r  = wr;
    float* w_out_r = wr + (size_t)D_MODEL * N_IN;

    static bool attr_done = false;
    if (!attr_done) {
        cudaFuncSetAttribute(gemm_tf32_kernel<true>,
                             cudaFuncAttributeMaxDynamicSharedMemorySize, GEMM_SMEM_BYTES);
        cudaFuncSetAttribute(gemm_tf32_kernel<false>,
                             cudaFuncAttributeMaxDynamicSharedMemorySize, GEMM_SMEM_BYTES);
        attr_done = true;
    }

    // Pre-round weights only (x is rounded in-register inside GEMM1)
    {
        int n4 = (D_MODEL * N_IN) / 4;
        round_tf32_kernel<<<(n4 + 255) / 256, 256>>>(W_in, w_in_r, n4);
        n4 = (D_INNER * D_MODEL) / 4;
        round_tf32_kernel<<<(n4 + 255) / 256, 256>>>(W_out, w_out_r, n4);
    }

    // GEMM1: xz = round(x) @ W_in_r   [32768,768] x [768,1536]
    {
        dim3 grid(N_IN / BN, M_TOT / BM);
        gemm_tf32_kernel<true><<<grid, 256, GEMM_SMEM_BYTES>>>(
            x, w_in_r, xz, M_TOT, N_IN, D_MODEL);
    }
    // Scan pipeline
    {
        dim3 grid(NCHUNK, BATCH);
        scan_partial_kernel<<<grid, 192>>>(xz, conv_w, conv_b, cs);
        scan_offsets_kernel<<<dim3(D_INNER / 4, BATCH), NCHUNK>>>(cs);
        scan_apply_kernel<<<grid, 192>>>(xz, conv_w, conv_b, Bm, Cm, Dv, cs, yz);
    }
    // GEMM2: out = yz @ W_out_r  [32768,768] x [768,768]
    {
        dim3 grid(D_MODEL / BN, M_TOT / BM);
        gemm_tf32_kernel<false><<<grid, 256, GEMM_SMEM_BYTES>>>(
            yz, w_out_r, out, M_TOT, D_MODEL, D_INNER);
    }
}